// round 2
// baseline (speedup 1.0000x reference)
#include <cuda_runtime.h>
#include <cuda_bf16.h>
#include <mma.h>

using namespace nvcuda;

// Problem dims
constexpr int Bq = 16, Cc = 512, Nn = 4096;

// Scratch (device globals — no allocation allowed)
__device__ __align__(16) __nv_bfloat16 g_embh[2][Bq][Cc][Nn];   // bf16 copies of rgb/geo, [src][b][c][n]
__device__ __align__(16) __nv_bfloat16 g_qkv[6][Bq][Cc][Nn];    // 0:Qp2r 1:Kp2r 2:Vp2r 3:Qr2p 4:Kr2p 5:Vr2p
__device__ __align__(16) __nv_bfloat16 g_wbf[8][Cc][Cc];        // 0..5 qkv weights, 6:proj_p2r 7:proj_r2p
__device__ __align__(16) float        g_outT[2][Bq][Cc][Nn];    // attention outputs per branch, [c][n]

typedef __nv_bfloat16 bft;

// ---------------------------------------------------------------------------
// K1a: convert embeddings fp32 -> bf16
// ---------------------------------------------------------------------------
__global__ void k_convert(const float* __restrict__ rgb, const float* __restrict__ geo) {
    size_t i = (size_t)(blockIdx.x * blockDim.x + threadIdx.x) * 4;
    float4 a = *reinterpret_cast<const float4*>(rgb + i);
    float4 b = *reinterpret_cast<const float4*>(geo + i);
    __nv_bfloat162* pr = reinterpret_cast<__nv_bfloat162*>(&g_embh[0][0][0][0] + i);
    __nv_bfloat162* pg = reinterpret_cast<__nv_bfloat162*>(&g_embh[1][0][0][0] + i);
    pr[0] = __floats2bfloat162_rn(a.x, a.y);
    pr[1] = __floats2bfloat162_rn(a.z, a.w);
    pg[0] = __floats2bfloat162_rn(b.x, b.y);
    pg[1] = __floats2bfloat162_rn(b.z, b.w);
}

// K1b: convert 8 weight matrices fp32 -> bf16
__global__ void k_convw(const float* w0, const float* w1, const float* w2, const float* w3,
                        const float* w4, const float* w5, const float* w6, const float* w7) {
    const float* ws[8] = {w0, w1, w2, w3, w4, w5, w6, w7};
    const int s = blockIdx.y;
    size_t i = (size_t)(blockIdx.x * blockDim.x + threadIdx.x) * 4;
    float4 a = *reinterpret_cast<const float4*>(ws[s] + i);
    __nv_bfloat162* p = reinterpret_cast<__nv_bfloat162*>(&g_wbf[s][0][0] + i);
    p[0] = __floats2bfloat162_rn(a.x, a.y);
    p[1] = __floats2bfloat162_rn(a.z, a.w);
}

// ---------------------------------------------------------------------------
// K2: QKV projections.  C[512,4096] = W[512,512] @ X[512,4096], bf16 in/out,
// fp32 accumulate.  Block tile 128x128, BK=32, 8 warps (4x2), double-buffered.
// gridDim = (32 n-tiles, 4 m-tiles, 96 = combo*16+batch)
// ---------------------------------------------------------------------------
__global__ __launch_bounds__(256) void k_gemm_qkv() {
    __shared__ __align__(16) char smraw[2 * 128 * 40 * 2 + 2 * 32 * 136 * 2];
    bft (*As)[128][40] = reinterpret_cast<bft (*)[128][40]>(smraw);
    bft (*Bs)[32][136] = reinterpret_cast<bft (*)[32][136]>(smraw + 2 * 128 * 40 * sizeof(bft));
    float* Cs = reinterpret_cast<float*>(smraw);  // reused after k-loop (32KB <= 37.9KB)

    const int z = blockIdx.z;
    const int combo = z >> 4, bb = z & 15;
    const int geo_src = (combo >= 1 && combo <= 3) ? 1 : 0;
    const bft* __restrict__ Ag = &g_wbf[combo][0][0];
    const bft* __restrict__ Bg = &g_embh[geo_src][bb][0][0];
    bft* __restrict__ Cg = &g_qkv[combo][bb][0][0];
    const int m0 = blockIdx.y * 128, n0 = blockIdx.x * 128;
    const int tid = threadIdx.x, wid = tid >> 5, lane = tid & 31;
    const int wm = (wid & 3) * 32, wn = (wid >> 2) * 64;

    wmma::fragment<wmma::accumulator, 16, 16, 16, float> acc[2][4];
#pragma unroll
    for (int i = 0; i < 2; i++)
#pragma unroll
        for (int j = 0; j < 4; j++) wmma::fill_fragment(acc[i][j], 0.0f);

    uint4 ra[2], rb[2];
#pragma unroll
    for (int p = 0; p < 2; p++) {
        int g = tid + p * 256;
        ra[p] = *reinterpret_cast<const uint4*>(Ag + (m0 + (g >> 2)) * 512 + ((g & 3) * 8));
        rb[p] = *reinterpret_cast<const uint4*>(Bg + (size_t)(g >> 4) * 4096 + n0 + ((g & 15) * 8));
    }
#pragma unroll
    for (int p = 0; p < 2; p++) {
        int g = tid + p * 256;
        *reinterpret_cast<uint4*>(&As[0][g >> 2][(g & 3) * 8]) = ra[p];
        *reinterpret_cast<uint4*>(&Bs[0][g >> 4][(g & 15) * 8]) = rb[p];
    }
    __syncthreads();

    for (int it = 0; it < 16; ++it) {
        const int s = it & 1;
        if (it < 15) {
            const int k0 = (it + 1) * 32;
#pragma unroll
            for (int p = 0; p < 2; p++) {
                int g = tid + p * 256;
                ra[p] = *reinterpret_cast<const uint4*>(Ag + (m0 + (g >> 2)) * 512 + k0 + ((g & 3) * 8));
                rb[p] = *reinterpret_cast<const uint4*>(Bg + (size_t)(k0 + (g >> 4)) * 4096 + n0 + ((g & 15) * 8));
            }
        }
#pragma unroll
        for (int kk = 0; kk < 32; kk += 16) {
            wmma::fragment<wmma::matrix_a, 16, 16, 16, bft, wmma::row_major> af[2];
            wmma::fragment<wmma::matrix_b, 16, 16, 16, bft, wmma::row_major> bfg[4];
            wmma::load_matrix_sync(af[0], &As[s][wm][kk], 40);
            wmma::load_matrix_sync(af[1], &As[s][wm + 16][kk], 40);
#pragma unroll
            for (int j = 0; j < 4; j++)
                wmma::load_matrix_sync(bfg[j], &Bs[s][kk][wn + j * 16], 136);
#pragma unroll
            for (int i = 0; i < 2; i++)
#pragma unroll
                for (int j = 0; j < 4; j++)
                    wmma::mma_sync(acc[i][j], af[i], bfg[j], acc[i][j]);
        }
        if (it < 15) {
#pragma unroll
            for (int p = 0; p < 2; p++) {
                int g = tid + p * 256;
                *reinterpret_cast<uint4*>(&As[s ^ 1][g >> 2][(g & 3) * 8]) = ra[p];
                *reinterpret_cast<uint4*>(&Bs[s ^ 1][g >> 4][(g & 15) * 8]) = rb[p];
            }
        }
        __syncthreads();
    }

    // Epilogue: per-warp smem staging (reuses tile smem), convert fp32 -> bf16.
    float* Cw = Cs + wid * (16 * 64);
#pragma unroll
    for (int i = 0; i < 2; i++) {
#pragma unroll
        for (int j = 0; j < 4; j++)
            wmma::store_matrix_sync(Cw + j * 16, acc[i][j], 64, wmma::mem_row_major);
        __syncwarp();
        const int r = lane >> 1, c0 = (lane & 1) * 32;
        const float* src = Cw + r * 64 + c0;
        bft* dst = Cg + (size_t)(m0 + wm + i * 16 + r) * 4096 + n0 + wn + c0;
        uint4 o[4];
        __nv_bfloat162* ph = reinterpret_cast<__nv_bfloat162*>(o);
#pragma unroll
        for (int q = 0; q < 16; q++) ph[q] = __floats2bfloat162_rn(src[2 * q], src[2 * q + 1]);
#pragma unroll
        for (int q = 0; q < 4; q++) reinterpret_cast<uint4*>(dst)[q] = o[q];
        __syncwarp();
    }
}

// ---------------------------------------------------------------------------
// K3: XCA attention per (branch, batch, head).
// Phase 1: L[64,64] = Q[64,N] . K[64,N]^T  (wmma, k split between warp groups)
// Phase 2: softmax rows (fp32), probs -> bf16 smem
// Phase 3: OutT[64,N] = attn^T[64,64] @ V[64,N]
// grid = (8 heads, 16 batches, 2 branches), 256 threads
// ---------------------------------------------------------------------------
__global__ __launch_bounds__(256) void k_attn() {
    __shared__ float Ls[2][64][64];
    __shared__ bft Ps[64][64];
    const int h = blockIdx.x, bb = blockIdx.y, br = blockIdx.z;
    const bft* __restrict__ Q  = &g_qkv[br * 3 + 0][bb][h * 64][0];
    const bft* __restrict__ Kk = &g_qkv[br * 3 + 1][bb][h * 64][0];
    const bft* __restrict__ V  = &g_qkv[br * 3 + 2][bb][h * 64][0];
    float* __restrict__ O = &g_outT[br][bb][h * 64][0];
    const int tid = threadIdx.x, wid = tid >> 5;
    const int ms = (wid & 3) * 16, kh = wid >> 2;

    {
        wmma::fragment<wmma::accumulator, 16, 16, 16, float> acc[4];
#pragma unroll
        for (int j = 0; j < 4; j++) wmma::fill_fragment(acc[j], 0.0f);
        const int kbeg = kh * 2048, kend = kbeg + 2048;
        for (int k = kbeg; k < kend; k += 16) {
            wmma::fragment<wmma::matrix_a, 16, 16, 16, bft, wmma::row_major> af;
            wmma::load_matrix_sync(af, Q + (size_t)ms * 4096 + k, 4096);
#pragma unroll
            for (int j = 0; j < 4; j++) {
                wmma::fragment<wmma::matrix_b, 16, 16, 16, bft, wmma::col_major> bfr;
                wmma::load_matrix_sync(bfr, Kk + (size_t)(j * 16) * 4096 + k, 4096);
                wmma::mma_sync(acc[j], af, bfr, acc[j]);
            }
        }
#pragma unroll
        for (int j = 0; j < 4; j++)
            wmma::store_matrix_sync(&Ls[kh][ms][j * 16], acc[j], 64, wmma::mem_row_major);
    }
    __syncthreads();

    if (tid < 64) {
        const float scale = 0.125f;  // 64^-0.5
        float mx = -1e30f;
        for (int j = 0; j < 64; j++) {
            float v = (Ls[0][tid][j] + Ls[1][tid][j]) * scale;
            mx = fmaxf(mx, v);
        }
        float s = 0.f;
        for (int j = 0; j < 64; j++) {
            float v = (Ls[0][tid][j] + Ls[1][tid][j]) * scale;
            float e = expf(v - mx);
            Ls[0][tid][j] = e;
            s += e;
        }
        float inv = 1.0f / s;
        for (int j = 0; j < 64; j++)
            Ps[tid][j] = __float2bfloat16(Ls[0][tid][j] * inv);
    }
    __syncthreads();

    // attn^T @ V : A[e,d] = attn[d,e]  -> col_major fragment over Ps (lda=64)
    wmma::fragment<wmma::matrix_a, 16, 16, 16, bft, wmma::col_major> af[4][4];
#pragma unroll
    for (int e = 0; e < 4; e++)
#pragma unroll
        for (int d = 0; d < 4; d++)
            wmma::load_matrix_sync(af[e][d], &Ps[d * 16][e * 16], 64);

    const int nbase = wid * 512;
    for (int nc = 0; nc < 512; nc += 16) {
        wmma::fragment<wmma::accumulator, 16, 16, 16, float> oacc[4];
#pragma unroll
        for (int e = 0; e < 4; e++) wmma::fill_fragment(oacc[e], 0.0f);
#pragma unroll
        for (int d = 0; d < 4; d++) {
            wmma::fragment<wmma::matrix_b, 16, 16, 16, bft, wmma::row_major> bfr;
            wmma::load_matrix_sync(bfr, V + (size_t)(d * 16) * 4096 + nbase + nc, 4096);
#pragma unroll
            for (int e = 0; e < 4; e++)
                wmma::mma_sync(oacc[e], af[e][d], bfr, oacc[e]);
        }
#pragma unroll
        for (int e = 0; e < 4; e++)
            wmma::store_matrix_sync(O + (size_t)(e * 16) * 4096 + nbase + nc, oacc[e], 4096,
                                    wmma::mem_row_major);
    }
}

// ---------------------------------------------------------------------------
// K4: fused output projections:  out[b] = proj_p2r @ OutT0[b] + proj_r2p @ OutT1[b]
// Same tiling as K2; 32 macro-iterations (2 branches x 16 k-steps); B converted
// fp32->bf16 while staging.  Stores fp32 directly to d_out.
// grid = (32, 4, 16)
// ---------------------------------------------------------------------------
__global__ __launch_bounds__(256) void k_gemm_final(float* __restrict__ out) {
    __shared__ __align__(16) char smraw[2 * 128 * 40 * 2 + 2 * 32 * 136 * 2];
    bft (*As)[128][40] = reinterpret_cast<bft (*)[128][40]>(smraw);
    bft (*Bs)[32][136] = reinterpret_cast<bft (*)[32][136]>(smraw + 2 * 128 * 40 * sizeof(bft));

    const int bb = blockIdx.z;
    const int m0 = blockIdx.y * 128, n0 = blockIdx.x * 128;
    const int tid = threadIdx.x, wid = tid >> 5;
    const int wm = (wid & 3) * 32, wn = (wid >> 2) * 64;

    wmma::fragment<wmma::accumulator, 16, 16, 16, float> acc[2][4];
#pragma unroll
    for (int i = 0; i < 2; i++)
#pragma unroll
        for (int j = 0; j < 4; j++) wmma::fill_fragment(acc[i][j], 0.0f);

    uint4 ra[2], rb[2];
    auto loadRegs = [&](int mi) {
        const int br = mi >> 4, k0 = (mi & 15) * 32;
        const bft* Ag = &g_wbf[6 + br][0][0];
        const float* Bsrc = &g_outT[br][bb][0][0];
#pragma unroll
        for (int p = 0; p < 2; p++) {
            int g = tid + p * 256;
            ra[p] = *reinterpret_cast<const uint4*>(Ag + (m0 + (g >> 2)) * 512 + k0 + ((g & 3) * 8));
            const float* bp = Bsrc + (size_t)(k0 + (g >> 4)) * 4096 + n0 + ((g & 15) * 8);
            float4 f0 = *reinterpret_cast<const float4*>(bp);
            float4 f1 = *reinterpret_cast<const float4*>(bp + 4);
            __nv_bfloat162 h0 = __floats2bfloat162_rn(f0.x, f0.y);
            __nv_bfloat162 h1 = __floats2bfloat162_rn(f0.z, f0.w);
            __nv_bfloat162 h2 = __floats2bfloat162_rn(f1.x, f1.y);
            __nv_bfloat162 h3 = __floats2bfloat162_rn(f1.z, f1.w);
            rb[p].x = *reinterpret_cast<unsigned int*>(&h0);
            rb[p].y = *reinterpret_cast<unsigned int*>(&h1);
            rb[p].z = *reinterpret_cast<unsigned int*>(&h2);
            rb[p].w = *reinterpret_cast<unsigned int*>(&h3);
        }
    };
    auto storeRegs = [&](int s) {
#pragma unroll
        for (int p = 0; p < 2; p++) {
            int g = tid + p * 256;
            *reinterpret_cast<uint4*>(&As[s][g >> 2][(g & 3) * 8]) = ra[p];
            *reinterpret_cast<uint4*>(&Bs[s][g >> 4][(g & 15) * 8]) = rb[p];
        }
    };

    loadRegs(0);
    storeRegs(0);
    __syncthreads();

    for (int mi = 0; mi < 32; ++mi) {
        const int s = mi & 1;
        if (mi < 31) loadRegs(mi + 1);
#pragma unroll
        for (int kk = 0; kk < 32; kk += 16) {
            wmma::fragment<wmma::matrix_a, 16, 16, 16, bft, wmma::row_major> af[2];
            wmma::fragment<wmma::matrix_b, 16, 16, 16, bft, wmma::row_major> bfg[4];
            wmma::load_matrix_sync(af[0], &As[s][wm][kk], 40);
            wmma::load_matrix_sync(af[1], &As[s][wm + 16][kk], 40);
#pragma unroll
            for (int j = 0; j < 4; j++)
                wmma::load_matrix_sync(bfg[j], &Bs[s][kk][wn + j * 16], 136);
#pragma unroll
            for (int i = 0; i < 2; i++)
#pragma unroll
                for (int j = 0; j < 4; j++)
                    wmma::mma_sync(acc[i][j], af[i], bfg[j], acc[i][j]);
        }
        if (mi < 31) storeRegs(s ^ 1);
        __syncthreads();
    }

    float* ob = out + (size_t)bb * Cc * Nn;
#pragma unroll
    for (int i = 0; i < 2; i++)
#pragma unroll
        for (int j = 0; j < 4; j++)
            wmma::store_matrix_sync(ob + (size_t)(m0 + wm + i * 16) * 4096 + n0 + wn + j * 16,
                                    acc[i][j], 4096, wmma::mem_row_major);
}

// ---------------------------------------------------------------------------
// K5: epilogue — add the exact fp32 residual inputs: out += rgb_emb + geo_emb
// ---------------------------------------------------------------------------
__global__ void k_epi(const float* __restrict__ rgb, const float* __restrict__ geo,
                      float* __restrict__ out) {
    size_t i = (size_t)(blockIdx.x * blockDim.x + threadIdx.x) * 4;
    float4 o = *reinterpret_cast<const float4*>(out + i);
    float4 r = *reinterpret_cast<const float4*>(rgb + i);
    float4 g = *reinterpret_cast<const float4*>(geo + i);
    o.x += r.x + g.x;
    o.y += r.y + g.y;
    o.z += r.z + g.z;
    o.w += r.w + g.w;
    *reinterpret_cast<float4*>(out + i) = o;
}

// ---------------------------------------------------------------------------
// Launch.  Input order: 0 rgb_emb, 1 geo_emb, 2 wq_rgb, 3 wk_rgb, 4 wv_rgb,
// 5 wq_point, 6 wk_point, 7 wv_point, 8 proj_r2p, 9 proj_p2r.
// ---------------------------------------------------------------------------
extern "C" void kernel_launch(void* const* d_in, const int* in_sizes, int n_in,
                              void* d_out, int out_size) {
    const float* rgb = (const float*)d_in[0];
    const float* geo = (const float*)d_in[1];

    // converts
    k_convert<<<32768, 256>>>(rgb, geo);
    // weight slot order: 0 wq_rgb, 1 wk_point, 2 wv_point, 3 wq_point, 4 wk_rgb,
    //                    5 wv_rgb, 6 proj_p2r, 7 proj_r2p
    k_convw<<<dim3(256, 8), 256>>>((const float*)d_in[2], (const float*)d_in[6],
                                   (const float*)d_in[7], (const float*)d_in[5],
                                   (const float*)d_in[3], (const float*)d_in[4],
                                   (const float*)d_in[9], (const float*)d_in[8]);

    // QKV projections: 6 combos x 16 batches
    k_gemm_qkv<<<dim3(32, 4, 96), 256>>>();

    // attention per (branch, batch, head)
    k_attn<<<dim3(8, 16, 2), 256>>>();

    // fused output projections (both branches) -> d_out
    k_gemm_final<<<dim3(32, 4, 16), 256>>>((float*)d_out);

    // add residual inputs
    k_epi<<<32768, 256>>>(rgb, geo, (float*)d_out);
}

// round 3
// speedup vs baseline: 1.1315x; 1.1315x over previous
#include <cuda_runtime.h>
#include <cuda_bf16.h>
#include <mma.h>

using namespace nvcuda;
typedef __nv_bfloat16 bft;

constexpr int Bq = 16, Cc = 512, Nn = 4096;

// Scratch (device globals — no allocation allowed)
__device__ __align__(16) bft g_embh[2][Bq][Cc][Nn];   // bf16 rgb/geo
__device__ __align__(16) bft g_qkv[6][Bq][Cc][Nn];    // 0:Qp2r 1:Kp2r 2:Vp2r 3:Qr2p 4:Kr2p 5:Vr2p
__device__ __align__(16) bft g_wbf[8][Cc][Cc];        // 0..5 qkv weights, 6:proj_p2r 7:proj_r2p
__device__ __align__(16) bft g_outb[2][Bq][Cc][Nn];   // attention outputs per branch (bf16 now)

// ---------------------------------------------------------------------------
// cp.async helpers
// ---------------------------------------------------------------------------
__device__ __forceinline__ void cp16(void* s, const void* g) {
    unsigned ss = (unsigned)__cvta_generic_to_shared(s);
    asm volatile("cp.async.cg.shared.global [%0], [%1], 16;\n" ::"r"(ss), "l"(g));
}
__device__ __forceinline__ void cpcommit() { asm volatile("cp.async.commit_group;\n"); }
template <int W>
__device__ __forceinline__ void cpwait() { asm volatile("cp.async.wait_group %0;\n" ::"n"(W)); }

// ---------------------------------------------------------------------------
// K1a: convert embeddings fp32 -> bf16
// ---------------------------------------------------------------------------
__global__ void k_convert(const float* __restrict__ rgb, const float* __restrict__ geo) {
    size_t i = (size_t)(blockIdx.x * blockDim.x + threadIdx.x) * 4;
    float4 a = *reinterpret_cast<const float4*>(rgb + i);
    float4 b = *reinterpret_cast<const float4*>(geo + i);
    __nv_bfloat162* pr = reinterpret_cast<__nv_bfloat162*>(&g_embh[0][0][0][0] + i);
    __nv_bfloat162* pg = reinterpret_cast<__nv_bfloat162*>(&g_embh[1][0][0][0] + i);
    pr[0] = __floats2bfloat162_rn(a.x, a.y);
    pr[1] = __floats2bfloat162_rn(a.z, a.w);
    pg[0] = __floats2bfloat162_rn(b.x, b.y);
    pg[1] = __floats2bfloat162_rn(b.z, b.w);
}

// K1b: convert 8 weight matrices fp32 -> bf16
__global__ void k_convw(const float* w0, const float* w1, const float* w2, const float* w3,
                        const float* w4, const float* w5, const float* w6, const float* w7) {
    const float* ws[8] = {w0, w1, w2, w3, w4, w5, w6, w7};
    const int s = blockIdx.y;
    size_t i = (size_t)(blockIdx.x * blockDim.x + threadIdx.x) * 4;
    float4 a = *reinterpret_cast<const float4*>(ws[s] + i);
    __nv_bfloat162* p = reinterpret_cast<__nv_bfloat162*>(&g_wbf[s][0][0] + i);
    p[0] = __floats2bfloat162_rn(a.x, a.y);
    p[1] = __floats2bfloat162_rn(a.z, a.w);
}

// ---------------------------------------------------------------------------
// K2: QKV projections. C[512,4096] = W[512,512] @ X[512,4096].
// 128x128 tile, BK=64, cp.async double-buffered. grid=(32,4,96), 256 thr.
// dyn smem: As[2][128][72] (36864 B) + Bs[2][64][136] (34816 B) = 71680 B
// ---------------------------------------------------------------------------
__global__ __launch_bounds__(256) void k_gemm_qkv() {
    extern __shared__ char sm[];
    bft (*As)[128][72] = reinterpret_cast<bft (*)[128][72]>(sm);
    bft (*Bs)[64][136] = reinterpret_cast<bft (*)[64][136]>(sm + 36864);

    const int z = blockIdx.z;
    const int combo = z >> 4, bb = z & 15;
    const int geo_src = (combo >= 1 && combo <= 3) ? 1 : 0;
    const bft* __restrict__ Ag = &g_wbf[combo][0][0];
    const bft* __restrict__ Bg = &g_embh[geo_src][bb][0][0];
    bft* __restrict__ Cg = &g_qkv[combo][bb][0][0];
    const int m0 = blockIdx.y * 128, n0 = blockIdx.x * 128;
    const int tid = threadIdx.x, wid = tid >> 5, lane = tid & 31;
    const int wm = (wid & 3) * 32, wn = (wid >> 2) * 64;

    wmma::fragment<wmma::accumulator, 16, 16, 16, float> acc[2][4];
#pragma unroll
    for (int i = 0; i < 2; i++)
#pragma unroll
        for (int j = 0; j < 4; j++) wmma::fill_fragment(acc[i][j], 0.0f);

    auto preload = [&](int it, int buf) {
        const int k0 = it * 64;
#pragma unroll
        for (int p = 0; p < 4; p++) {
            int idx = tid + p * 256;
            int ar = idx >> 3, ac = (idx & 7) * 8;
            cp16(&As[buf][ar][ac], Ag + (m0 + ar) * 512 + k0 + ac);
            int br = idx >> 4, bc = (idx & 15) * 8;
            cp16(&Bs[buf][br][bc], Bg + (size_t)(k0 + br) * 4096 + n0 + bc);
        }
        cpcommit();
    };

    preload(0, 0);
    for (int it = 0; it < 8; ++it) {
        const int buf = it & 1;
        if (it < 7) { preload(it + 1, buf ^ 1); cpwait<1>(); }
        else        { cpwait<0>(); }
        __syncthreads();
#pragma unroll
        for (int kk = 0; kk < 64; kk += 16) {
            wmma::fragment<wmma::matrix_a, 16, 16, 16, bft, wmma::row_major> af[2];
            wmma::fragment<wmma::matrix_b, 16, 16, 16, bft, wmma::row_major> bfr[4];
            wmma::load_matrix_sync(af[0], &As[buf][wm][kk], 72);
            wmma::load_matrix_sync(af[1], &As[buf][wm + 16][kk], 72);
#pragma unroll
            for (int j = 0; j < 4; j++)
                wmma::load_matrix_sync(bfr[j], &Bs[buf][kk][wn + j * 16], 136);
#pragma unroll
            for (int i = 0; i < 2; i++)
#pragma unroll
                for (int j = 0; j < 4; j++)
                    wmma::mma_sync(acc[i][j], af[i], bfr[j], acc[i][j]);
        }
        __syncthreads();
    }

    // Epilogue: per-warp smem staging (aliases tile smem), fp32 -> bf16.
    float* Cw = reinterpret_cast<float*>(sm) + wid * 1024;
#pragma unroll
    for (int i = 0; i < 2; i++) {
#pragma unroll
        for (int j = 0; j < 4; j++)
            wmma::store_matrix_sync(Cw + j * 16, acc[i][j], 64, wmma::mem_row_major);
        __syncwarp();
        const int r = lane >> 1, c0 = (lane & 1) * 32;
        const float* src = Cw + r * 64 + c0;
        bft* dst = Cg + (size_t)(m0 + wm + i * 16 + r) * 4096 + n0 + wn + c0;
        uint4 o[4];
        __nv_bfloat162* ph = reinterpret_cast<__nv_bfloat162*>(o);
#pragma unroll
        for (int q = 0; q < 16; q++) ph[q] = __floats2bfloat162_rn(src[2 * q], src[2 * q + 1]);
#pragma unroll
        for (int q = 0; q < 4; q++) reinterpret_cast<uint4*>(dst)[q] = o[q];
        __syncwarp();
    }
}

// ---------------------------------------------------------------------------
// K3: XCA attention per (branch, batch, head), smem-staged via cp.async.
// Phase 1: S[64,64] = Q[64,N].K[64,N]^T, chunks of 128 over N, double buffer.
// Phase 2: fp32 softmax rows -> bf16 probs.
// Phase 3: OutT[64,N] = attn^T @ V, chunks of 128, output bf16.
// grid=(8,16,2), 256 thr.  dyn smem 111616 B:
//   QS[2][64][136] @0 (34816, aliased by VS in p3)
//   KS[2][64][136] @34816 (34816, aliased by output staging in p3)
//   Ls[2][64][64] fp32 @69632 (32768)
//   Ps[64][72] bf16 @102400 (9216)
// ---------------------------------------------------------------------------
__global__ __launch_bounds__(256) void k_attn() {
    extern __shared__ char sm[];
    bft (*QS)[64][136] = reinterpret_cast<bft (*)[64][136]>(sm);
    bft (*KS)[64][136] = reinterpret_cast<bft (*)[64][136]>(sm + 34816);
    float (*Ls)[64][64] = reinterpret_cast<float (*)[64][64]>(sm + 69632);
    bft (*Ps)[72] = reinterpret_cast<bft (*)[72]>(sm + 102400);

    const int h = blockIdx.x, bb = blockIdx.y, br = blockIdx.z;
    const bft* __restrict__ Q  = &g_qkv[br * 3 + 0][bb][h * 64][0];
    const bft* __restrict__ Kk = &g_qkv[br * 3 + 1][bb][h * 64][0];
    const bft* __restrict__ V  = &g_qkv[br * 3 + 2][bb][h * 64][0];
    bft* __restrict__ O = &g_outb[br][bb][h * 64][0];
    const int tid = threadIdx.x, wid = tid >> 5, lane = tid & 31;

    // ---- Phase 1: logits ----
    {
        const int wm = (wid & 3) * 16, kh = wid >> 2;
        wmma::fragment<wmma::accumulator, 16, 16, 16, float> acc[4];
#pragma unroll
        for (int j = 0; j < 4; j++) wmma::fill_fragment(acc[j], 0.0f);

        auto pre = [&](int c, int buf) {
#pragma unroll
            for (int p = 0; p < 4; p++) {
                int idx = tid + p * 256;
                int r = idx >> 4, cl = (idx & 15) * 8;
                cp16(&QS[buf][r][cl], Q + (size_t)r * 4096 + c * 128 + cl);
                cp16(&KS[buf][r][cl], Kk + (size_t)r * 4096 + c * 128 + cl);
            }
            cpcommit();
        };
        pre(0, 0);
        for (int c = 0; c < 32; ++c) {
            const int buf = c & 1;
            if (c < 31) { pre(c + 1, buf ^ 1); cpwait<1>(); }
            else        { cpwait<0>(); }
            __syncthreads();
#pragma unroll
            for (int ks = 0; ks < 4; ks++) {
                wmma::fragment<wmma::matrix_a, 16, 16, 16, bft, wmma::row_major> af;
                wmma::load_matrix_sync(af, &QS[buf][wm][kh * 64 + ks * 16], 136);
#pragma unroll
                for (int j = 0; j < 4; j++) {
                    wmma::fragment<wmma::matrix_b, 16, 16, 16, bft, wmma::col_major> bfr;
                    wmma::load_matrix_sync(bfr, &KS[buf][j * 16][kh * 64 + ks * 16], 136);
                    wmma::mma_sync(acc[j], af, bfr, acc[j]);
                }
            }
            __syncthreads();
        }
#pragma unroll
        for (int j = 0; j < 4; j++)
            wmma::store_matrix_sync(&Ls[kh][wm][j * 16], acc[j], 64, wmma::mem_row_major);
    }
    __syncthreads();

    // ---- Phase 2: softmax ----
    if (tid < 64) {
        const float scale = 0.125f;  // 64^-0.5
        float mx = -1e30f;
        for (int j = 0; j < 64; j++) {
            float v = (Ls[0][tid][j] + Ls[1][tid][j]) * scale;
            mx = fmaxf(mx, v);
        }
        float s = 0.f;
        for (int j = 0; j < 64; j++) {
            float v = (Ls[0][tid][j] + Ls[1][tid][j]) * scale;
            float e = __expf(v - mx);
            Ls[0][tid][j] = e;
            s += e;
        }
        float inv = 1.0f / s;
        for (int j = 0; j < 64; j++) Ps[tid][j] = __float2bfloat16(Ls[0][tid][j] * inv);
    }
    __syncthreads();

    // ---- Phase 3: OutT = attn^T @ V ----
    {
        bft (*VS)[64][136] = QS;                                 // alias
        float* OSw = reinterpret_cast<float*>(sm + 34816) + wid * 1024;  // 16x64 per warp
        const int we = (wid & 3), wn = (wid >> 2) * 64;

        wmma::fragment<wmma::matrix_a, 16, 16, 16, bft, wmma::col_major> af[4];
#pragma unroll
        for (int d = 0; d < 4; d++)
            wmma::load_matrix_sync(af[d], &Ps[d * 16][we * 16], 72);

        auto prev = [&](int c, int buf) {
#pragma unroll
            for (int p = 0; p < 4; p++) {
                int idx = tid + p * 256;
                int r = idx >> 4, cl = (idx & 15) * 8;
                cp16(&VS[buf][r][cl], V + (size_t)r * 4096 + c * 128 + cl);
            }
            cpcommit();
        };
        prev(0, 0);
        for (int c = 0; c < 32; ++c) {
            const int buf = c & 1;
            if (c < 31) { prev(c + 1, buf ^ 1); cpwait<1>(); }
            else        { cpwait<0>(); }
            __syncthreads();
#pragma unroll
            for (int nc = 0; nc < 4; nc++) {
                wmma::fragment<wmma::accumulator, 16, 16, 16, float> oa;
                wmma::fill_fragment(oa, 0.0f);
#pragma unroll
                for (int d = 0; d < 4; d++) {
                    wmma::fragment<wmma::matrix_b, 16, 16, 16, bft, wmma::row_major> bfr;
                    wmma::load_matrix_sync(bfr, &VS[buf][d * 16][wn + nc * 16], 136);
                    wmma::mma_sync(oa, af[d], bfr, oa);
                }
                wmma::store_matrix_sync(OSw + nc * 16, oa, 64, wmma::mem_row_major);
            }
            __syncwarp();
            {
                const int r = lane >> 1, c0 = (lane & 1) * 32;
                const float* src = OSw + r * 64 + c0;
                bft* dst = O + (size_t)(we * 16 + r) * 4096 + c * 128 + wn + c0;
                uint4 o[4];
                __nv_bfloat162* ph = reinterpret_cast<__nv_bfloat162*>(o);
#pragma unroll
                for (int q = 0; q < 16; q++) ph[q] = __floats2bfloat162_rn(src[2 * q], src[2 * q + 1]);
#pragma unroll
                for (int q = 0; q < 4; q++) reinterpret_cast<uint4*>(dst)[q] = o[q];
            }
            __syncwarp();
            __syncthreads();
        }
    }
}

// ---------------------------------------------------------------------------
// K4: fused output projections + residual:
//   out[b] = proj_p2r @ OutT0[b] + proj_r2p @ OutT1[b] + rgb[b] + geo[b]
// 16 macro-iters (2 branches x 8 k-steps of 64). grid=(32,4,16), 256 thr.
// ---------------------------------------------------------------------------
__global__ __launch_bounds__(256) void k_gemm_final(const float* __restrict__ rgb,
                                                    const float* __restrict__ geo,
                                                    float* __restrict__ out) {
    extern __shared__ char sm[];
    bft (*As)[128][72] = reinterpret_cast<bft (*)[128][72]>(sm);
    bft (*Bs)[64][136] = reinterpret_cast<bft (*)[64][136]>(sm + 36864);

    const int bb = blockIdx.z;
    const int m0 = blockIdx.y * 128, n0 = blockIdx.x * 128;
    const int tid = threadIdx.x, wid = tid >> 5, lane = tid & 31;
    const int wm = (wid & 3) * 32, wn = (wid >> 2) * 64;

    wmma::fragment<wmma::accumulator, 16, 16, 16, float> acc[2][4];
#pragma unroll
    for (int i = 0; i < 2; i++)
#pragma unroll
        for (int j = 0; j < 4; j++) wmma::fill_fragment(acc[i][j], 0.0f);

    auto pre = [&](int mi, int buf) {
        const int brn = mi >> 3, k0 = (mi & 7) * 64;
        const bft* Ag = &g_wbf[6 + brn][0][0];
        const bft* Bg = &g_outb[brn][bb][0][0];
#pragma unroll
        for (int p = 0; p < 4; p++) {
            int idx = tid + p * 256;
            int ar = idx >> 3, ac = (idx & 7) * 8;
            cp16(&As[buf][ar][ac], Ag + (m0 + ar) * 512 + k0 + ac);
            int brr = idx >> 4, bc = (idx & 15) * 8;
            cp16(&Bs[buf][brr][bc], Bg + (size_t)(k0 + brr) * 4096 + n0 + bc);
        }
        cpcommit();
    };

    pre(0, 0);
    for (int mi = 0; mi < 16; ++mi) {
        const int buf = mi & 1;
        if (mi < 15) { pre(mi + 1, buf ^ 1); cpwait<1>(); }
        else         { cpwait<0>(); }
        __syncthreads();
#pragma unroll
        for (int kk = 0; kk < 64; kk += 16) {
            wmma::fragment<wmma::matrix_a, 16, 16, 16, bft, wmma::row_major> af[2];
            wmma::fragment<wmma::matrix_b, 16, 16, 16, bft, wmma::row_major> bfr[4];
            wmma::load_matrix_sync(af[0], &As[buf][wm][kk], 72);
            wmma::load_matrix_sync(af[1], &As[buf][wm + 16][kk], 72);
#pragma unroll
            for (int j = 0; j < 4; j++)
                wmma::load_matrix_sync(bfr[j], &Bs[buf][kk][wn + j * 16], 136);
#pragma unroll
            for (int i = 0; i < 2; i++)
#pragma unroll
                for (int j = 0; j < 4; j++)
                    wmma::mma_sync(acc[i][j], af[i], bfr[j], acc[i][j]);
        }
        __syncthreads();
    }

    // Epilogue: out = acc + rgb + geo (all fp32)
    float* Cw = reinterpret_cast<float*>(sm) + wid * 1024;
    const size_t bplane = (size_t)bb * Cc * Nn;
#pragma unroll
    for (int i = 0; i < 2; i++) {
#pragma unroll
        for (int j = 0; j < 4; j++)
            wmma::store_matrix_sync(Cw + j * 16, acc[i][j], 64, wmma::mem_row_major);
        __syncwarp();
        const int r = lane >> 1, c0 = (lane & 1) * 32;
        const float* src = Cw + r * 64 + c0;
        const size_t off = bplane + (size_t)(m0 + wm + i * 16 + r) * 4096 + n0 + wn + c0;
#pragma unroll
        for (int q = 0; q < 8; q++) {
            float4 a = reinterpret_cast<const float4*>(src)[q];
            float4 rr = reinterpret_cast<const float4*>(rgb + off)[q];
            float4 gg = reinterpret_cast<const float4*>(geo + off)[q];
            a.x += rr.x + gg.x;
            a.y += rr.y + gg.y;
            a.z += rr.z + gg.z;
            a.w += rr.w + gg.w;
            reinterpret_cast<float4*>(out + off)[q] = a;
        }
        __syncwarp();
    }
}

// ---------------------------------------------------------------------------
// Launch. Input order: 0 rgb_emb, 1 geo_emb, 2 wq_rgb, 3 wk_rgb, 4 wv_rgb,
// 5 wq_point, 6 wk_point, 7 wv_point, 8 proj_r2p, 9 proj_p2r.
// ---------------------------------------------------------------------------
extern "C" void kernel_launch(void* const* d_in, const int* in_sizes, int n_in,
                              void* d_out, int out_size) {
    const float* rgb = (const float*)d_in[0];
    const float* geo = (const float*)d_in[1];

    cudaFuncSetAttribute(k_gemm_qkv, cudaFuncAttributeMaxDynamicSharedMemorySize, 71680);
    cudaFuncSetAttribute(k_gemm_final, cudaFuncAttributeMaxDynamicSharedMemorySize, 71680);
    cudaFuncSetAttribute(k_attn, cudaFuncAttributeMaxDynamicSharedMemorySize, 111616);

    k_convert<<<32768, 256>>>(rgb, geo);
    // weight slot order: 0 wq_rgb, 1 wk_point, 2 wv_point, 3 wq_point, 4 wk_rgb,
    //                    5 wv_rgb, 6 proj_p2r, 7 proj_r2p
    k_convw<<<dim3(256, 8), 256>>>((const float*)d_in[2], (const float*)d_in[6],
                                   (const float*)d_in[7], (const float*)d_in[5],
                                   (const float*)d_in[3], (const float*)d_in[4],
                                   (const float*)d_in[9], (const float*)d_in[8]);

    // QKV projections: 6 combos x 16 batches
    k_gemm_qkv<<<dim3(32, 4, 96), 256, 71680>>>();

    // attention per (branch, batch, head)
    k_attn<<<dim3(8, 16, 2), 256, 111616>>>();

    // fused output projections + residual -> d_out
    k_gemm_final<<<dim3(32, 4, 16), 256, 71680>>>(rgb, geo, (float*)d_out);
}

// round 4
// speedup vs baseline: 1.1317x; 1.0003x over previous
#include <cuda_runtime.h>
#include <cuda_bf16.h>
#include <mma.h>

using namespace nvcuda;
typedef __nv_bfloat16 bft;

constexpr int Bq = 16, Cc = 512, Nn = 4096;

// Scratch (device globals — no allocation allowed)
__device__ __align__(16) bft g_embh[2][Bq][Cc][Nn];   // bf16 rgb/geo
__device__ __align__(16) bft g_qkv[6][Bq][Cc][Nn];    // 0:Qp2r 1:Kp2r 2:Vp2r 3:Qr2p 4:Kr2p 5:Vr2p
__device__ __align__(16) bft g_wbf[8][Cc][Cc];        // 0..5 qkv weights, 6:proj_p2r 7:proj_r2p
__device__ __align__(16) bft g_outb[2][Bq][Cc][Nn];   // attention outputs per branch (bf16 now)

// ---------------------------------------------------------------------------
// cp.async helpers
// ---------------------------------------------------------------------------
__device__ __forceinline__ void cp16(void* s, const void* g) {
    unsigned ss = (unsigned)__cvta_generic_to_shared(s);
    asm volatile("cp.async.cg.shared.global [%0], [%1], 16;\n" ::"r"(ss), "l"(g));
}
__device__ __forceinline__ void cpcommit() { asm volatile("cp.async.commit_group;\n"); }
template <int W>
__device__ __forceinline__ void cpwait() { asm volatile("cp.async.wait_group %0;\n" ::"n"(W)); }

// ---------------------------------------------------------------------------
// K1a: convert embeddings fp32 -> bf16
// ---------------------------------------------------------------------------
__global__ void k_convert(const float* __restrict__ rgb, const float* __restrict__ geo) {
    size_t i = (size_t)(blockIdx.x * blockDim.x + threadIdx.x) * 4;
    float4 a = *reinterpret_cast<const float4*>(rgb + i);
    float4 b = *reinterpret_cast<const float4*>(geo + i);
    __nv_bfloat162* pr = reinterpret_cast<__nv_bfloat162*>(&g_embh[0][0][0][0] + i);
    __nv_bfloat162* pg = reinterpret_cast<__nv_bfloat162*>(&g_embh[1][0][0][0] + i);
    pr[0] = __floats2bfloat162_rn(a.x, a.y);
    pr[1] = __floats2bfloat162_rn(a.z, a.w);
    pg[0] = __floats2bfloat162_rn(b.x, b.y);
    pg[1] = __floats2bfloat162_rn(b.z, b.w);
}

// K1b: convert 8 weight matrices fp32 -> bf16
__global__ void k_convw(const float* w0, const float* w1, const float* w2, const float* w3,
                        const float* w4, const float* w5, const float* w6, const float* w7) {
    const float* ws[8] = {w0, w1, w2, w3, w4, w5, w6, w7};
    const int s = blockIdx.y;
    size_t i = (size_t)(blockIdx.x * blockDim.x + threadIdx.x) * 4;
    float4 a = *reinterpret_cast<const float4*>(ws[s] + i);
    __nv_bfloat162* p = reinterpret_cast<__nv_bfloat162*>(&g_wbf[s][0][0] + i);
    p[0] = __floats2bfloat162_rn(a.x, a.y);
    p[1] = __floats2bfloat162_rn(a.z, a.w);
}

// ---------------------------------------------------------------------------
// K2: QKV projections. C[512,4096] = W[512,512] @ X[512,4096].
// 128x128 tile, BK=64, cp.async double-buffered. grid=(32,4,96), 256 thr.
// dyn smem: As[2][128][72] (36864 B) + Bs[2][64][136] (34816 B) = 71680 B
// ---------------------------------------------------------------------------
__global__ __launch_bounds__(256) void k_gemm_qkv() {
    extern __shared__ char sm[];
    bft (*As)[128][72] = reinterpret_cast<bft (*)[128][72]>(sm);
    bft (*Bs)[64][136] = reinterpret_cast<bft (*)[64][136]>(sm + 36864);

    const int z = blockIdx.z;
    const int combo = z >> 4, bb = z & 15;
    const int geo_src = (combo >= 1 && combo <= 3) ? 1 : 0;
    const bft* __restrict__ Ag = &g_wbf[combo][0][0];
    const bft* __restrict__ Bg = &g_embh[geo_src][bb][0][0];
    bft* __restrict__ Cg = &g_qkv[combo][bb][0][0];
    const int m0 = blockIdx.y * 128, n0 = blockIdx.x * 128;
    const int tid = threadIdx.x, wid = tid >> 5, lane = tid & 31;
    const int wm = (wid & 3) * 32, wn = (wid >> 2) * 64;

    wmma::fragment<wmma::accumulator, 16, 16, 16, float> acc[2][4];
#pragma unroll
    for (int i = 0; i < 2; i++)
#pragma unroll
        for (int j = 0; j < 4; j++) wmma::fill_fragment(acc[i][j], 0.0f);

    auto preload = [&](int it, int buf) {
        const int k0 = it * 64;
#pragma unroll
        for (int p = 0; p < 4; p++) {
            int idx = tid + p * 256;
            int ar = idx >> 3, ac = (idx & 7) * 8;
            cp16(&As[buf][ar][ac], Ag + (m0 + ar) * 512 + k0 + ac);
            int br = idx >> 4, bc = (idx & 15) * 8;
            cp16(&Bs[buf][br][bc], Bg + (size_t)(k0 + br) * 4096 + n0 + bc);
        }
        cpcommit();
    };

    preload(0, 0);
    for (int it = 0; it < 8; ++it) {
        const int buf = it & 1;
        if (it < 7) { preload(it + 1, buf ^ 1); cpwait<1>(); }
        else        { cpwait<0>(); }
        __syncthreads();
#pragma unroll
        for (int kk = 0; kk < 64; kk += 16) {
            wmma::fragment<wmma::matrix_a, 16, 16, 16, bft, wmma::row_major> af[2];
            wmma::fragment<wmma::matrix_b, 16, 16, 16, bft, wmma::row_major> bfr[4];
            wmma::load_matrix_sync(af[0], &As[buf][wm][kk], 72);
            wmma::load_matrix_sync(af[1], &As[buf][wm + 16][kk], 72);
#pragma unroll
            for (int j = 0; j < 4; j++)
                wmma::load_matrix_sync(bfr[j], &Bs[buf][kk][wn + j * 16], 136);
#pragma unroll
            for (int i = 0; i < 2; i++)
#pragma unroll
                for (int j = 0; j < 4; j++)
                    wmma::mma_sync(acc[i][j], af[i], bfr[j], acc[i][j]);
        }
        __syncthreads();
    }

    // Epilogue: per-warp smem staging (aliases tile smem), fp32 -> bf16.
    float* Cw = reinterpret_cast<float*>(sm) + wid * 1024;
#pragma unroll
    for (int i = 0; i < 2; i++) {
#pragma unroll
        for (int j = 0; j < 4; j++)
            wmma::store_matrix_sync(Cw + j * 16, acc[i][j], 64, wmma::mem_row_major);
        __syncwarp();
        const int r = lane >> 1, c0 = (lane & 1) * 32;
        const float* src = Cw + r * 64 + c0;
        bft* dst = Cg + (size_t)(m0 + wm + i * 16 + r) * 4096 + n0 + wn + c0;
        uint4 o[4];
        __nv_bfloat162* ph = reinterpret_cast<__nv_bfloat162*>(o);
#pragma unroll
        for (int q = 0; q < 16; q++) ph[q] = __floats2bfloat162_rn(src[2 * q], src[2 * q + 1]);
#pragma unroll
        for (int q = 0; q < 4; q++) reinterpret_cast<uint4*>(dst)[q] = o[q];
        __syncwarp();
    }
}

// ---------------------------------------------------------------------------
// K3: XCA attention per (branch, batch, head), smem-staged via cp.async.
// Phase 1: S[64,64] = Q[64,N].K[64,N]^T, chunks of 128 over N, double buffer.
// Phase 2: fp32 softmax rows -> bf16 probs.
// Phase 3: OutT[64,N] = attn^T @ V, chunks of 128, output bf16.
// grid=(8,16,2), 256 thr.  dyn smem 111616 B:
//   QS[2][64][136] @0 (34816, aliased by VS in p3)
//   KS[2][64][136] @34816 (34816, aliased by output staging in p3)
//   Ls[2][64][64] fp32 @69632 (32768)
//   Ps[64][72] bf16 @102400 (9216)
// ---------------------------------------------------------------------------
__global__ __launch_bounds__(256) void k_attn() {
    extern __shared__ char sm[];
    bft (*QS)[64][136] = reinterpret_cast<bft (*)[64][136]>(sm);
    bft (*KS)[64][136] = reinterpret_cast<bft (*)[64][136]>(sm + 34816);
    float (*Ls)[64][64] = reinterpret_cast<float (*)[64][64]>(sm + 69632);
    bft (*Ps)[72] = reinterpret_cast<bft (*)[72]>(sm + 102400);

    const int h = blockIdx.x, bb = blockIdx.y, br = blockIdx.z;
    const bft* __restrict__ Q  = &g_qkv[br * 3 + 0][bb][h * 64][0];
    const bft* __restrict__ Kk = &g_qkv[br * 3 + 1][bb][h * 64][0];
    const bft* __restrict__ V  = &g_qkv[br * 3 + 2][bb][h * 64][0];
    bft* __restrict__ O = &g_outb[br][bb][h * 64][0];
    const int tid = threadIdx.x, wid = tid >> 5, lane = tid & 31;

    // ---- Phase 1: logits ----
    {
        const int wm = (wid & 3) * 16, kh = wid >> 2;
        wmma::fragment<wmma::accumulator, 16, 16, 16, float> acc[4];
#pragma unroll
        for (int j = 0; j < 4; j++) wmma::fill_fragment(acc[j], 0.0f);

        auto pre = [&](int c, int buf) {
#pragma unroll
            for (int p = 0; p < 4; p++) {
                int idx = tid + p * 256;
                int r = idx >> 4, cl = (idx & 15) * 8;
                cp16(&QS[buf][r][cl], Q + (size_t)r * 4096 + c * 128 + cl);
                cp16(&KS[buf][r][cl], Kk + (size_t)r * 4096 + c * 128 + cl);
            }
            cpcommit();
        };
        pre(0, 0);
        for (int c = 0; c < 32; ++c) {
            const int buf = c & 1;
            if (c < 31) { pre(c + 1, buf ^ 1); cpwait<1>(); }
            else        { cpwait<0>(); }
            __syncthreads();
#pragma unroll
            for (int ks = 0; ks < 4; ks++) {
                wmma::fragment<wmma::matrix_a, 16, 16, 16, bft, wmma::row_major> af;
                wmma::load_matrix_sync(af, &QS[buf][wm][kh * 64 + ks * 16], 136);
#pragma unroll
                for (int j = 0; j < 4; j++) {
                    wmma::fragment<wmma::matrix_b, 16, 16, 16, bft, wmma::col_major> bfr;
                    wmma::load_matrix_sync(bfr, &KS[buf][j * 16][kh * 64 + ks * 16], 136);
                    wmma::mma_sync(acc[j], af, bfr, acc[j]);
                }
            }
            __syncthreads();
        }
#pragma unroll
        for (int j = 0; j < 4; j++)
            wmma::store_matrix_sync(&Ls[kh][wm][j * 16], acc[j], 64, wmma::mem_row_major);
    }
    __syncthreads();

    // ---- Phase 2: softmax ----
    if (tid < 64) {
        const float scale = 0.125f;  // 64^-0.5
        float mx = -1e30f;
        for (int j = 0; j < 64; j++) {
            float v = (Ls[0][tid][j] + Ls[1][tid][j]) * scale;
            mx = fmaxf(mx, v);
        }
        float s = 0.f;
        for (int j = 0; j < 64; j++) {
            float v = (Ls[0][tid][j] + Ls[1][tid][j]) * scale;
            float e = __expf(v - mx);
            Ls[0][tid][j] = e;
            s += e;
        }
        float inv = 1.0f / s;
        for (int j = 0; j < 64; j++) Ps[tid][j] = __float2bfloat16(Ls[0][tid][j] * inv);
    }
    __syncthreads();

    // ---- Phase 3: OutT = attn^T @ V ----
    {
        bft (*VS)[64][136] = QS;                                 // alias
        float* OSw = reinterpret_cast<float*>(sm + 34816) + wid * 1024;  // 16x64 per warp
        const int we = (wid & 3), wn = (wid >> 2) * 64;

        wmma::fragment<wmma::matrix_a, 16, 16, 16, bft, wmma::col_major> af[4];
#pragma unroll
        for (int d = 0; d < 4; d++)
            wmma::load_matrix_sync(af[d], &Ps[d * 16][we * 16], 72);

        auto prev = [&](int c, int buf) {
#pragma unroll
            for (int p = 0; p < 4; p++) {
                int idx = tid + p * 256;
                int r = idx >> 4, cl = (idx & 15) * 8;
                cp16(&VS[buf][r][cl], V + (size_t)r * 4096 + c * 128 + cl);
            }
            cpcommit();
        };
        prev(0, 0);
        for (int c = 0; c < 32; ++c) {
            const int buf = c & 1;
            if (c < 31) { prev(c + 1, buf ^ 1); cpwait<1>(); }
            else        { cpwait<0>(); }
            __syncthreads();
#pragma unroll
            for (int nc = 0; nc < 4; nc++) {
                wmma::fragment<wmma::accumulator, 16, 16, 16, float> oa;
                wmma::fill_fragment(oa, 0.0f);
#pragma unroll
                for (int d = 0; d < 4; d++) {
                    wmma::fragment<wmma::matrix_b, 16, 16, 16, bft, wmma::row_major> bfr;
                    wmma::load_matrix_sync(bfr, &VS[buf][d * 16][wn + nc * 16], 136);
                    wmma::mma_sync(oa, af[d], bfr, oa);
                }
                wmma::store_matrix_sync(OSw + nc * 16, oa, 64, wmma::mem_row_major);
            }
            __syncwarp();
            {
                const int r = lane >> 1, c0 = (lane & 1) * 32;
                const float* src = OSw + r * 64 + c0;
                bft* dst = O + (size_t)(we * 16 + r) * 4096 + c * 128 + wn + c0;
                uint4 o[4];
                __nv_bfloat162* ph = reinterpret_cast<__nv_bfloat162*>(o);
#pragma unroll
                for (int q = 0; q < 16; q++) ph[q] = __floats2bfloat162_rn(src[2 * q], src[2 * q + 1]);
#pragma unroll
                for (int q = 0; q < 4; q++) reinterpret_cast<uint4*>(dst)[q] = o[q];
            }
            __syncwarp();
            __syncthreads();
        }
    }
}

// ---------------------------------------------------------------------------
// K4: fused output projections + residual:
//   out[b] = proj_p2r @ OutT0[b] + proj_r2p @ OutT1[b] + rgb[b] + geo[b]
// 16 macro-iters (2 branches x 8 k-steps of 64). grid=(32,4,16), 256 thr.
// ---------------------------------------------------------------------------
__global__ __launch_bounds__(256) void k_gemm_final(const float* __restrict__ rgb,
                                                    const float* __restrict__ geo,
                                                    float* __restrict__ out) {
    extern __shared__ char sm[];
    bft (*As)[128][72] = reinterpret_cast<bft (*)[128][72]>(sm);
    bft (*Bs)[64][136] = reinterpret_cast<bft (*)[64][136]>(sm + 36864);

    const int bb = blockIdx.z;
    const int m0 = blockIdx.y * 128, n0 = blockIdx.x * 128;
    const int tid = threadIdx.x, wid = tid >> 5, lane = tid & 31;
    const int wm = (wid & 3) * 32, wn = (wid >> 2) * 64;

    wmma::fragment<wmma::accumulator, 16, 16, 16, float> acc[2][4];
#pragma unroll
    for (int i = 0; i < 2; i++)
#pragma unroll
        for (int j = 0; j < 4; j++) wmma::fill_fragment(acc[i][j], 0.0f);

    auto pre = [&](int mi, int buf) {
        const int brn = mi >> 3, k0 = (mi & 7) * 64;
        const bft* Ag = &g_wbf[6 + brn][0][0];
        const bft* Bg = &g_outb[brn][bb][0][0];
#pragma unroll
        for (int p = 0; p < 4; p++) {
            int idx = tid + p * 256;
            int ar = idx >> 3, ac = (idx & 7) * 8;
            cp16(&As[buf][ar][ac], Ag + (m0 + ar) * 512 + k0 + ac);
            int brr = idx >> 4, bc = (idx & 15) * 8;
            cp16(&Bs[buf][brr][bc], Bg + (size_t)(k0 + brr) * 4096 + n0 + bc);
        }
        cpcommit();
    };

    pre(0, 0);
    for (int mi = 0; mi < 16; ++mi) {
        const int buf = mi & 1;
        if (mi < 15) { pre(mi + 1, buf ^ 1); cpwait<1>(); }
        else         { cpwait<0>(); }
        __syncthreads();
#pragma unroll
        for (int kk = 0; kk < 64; kk += 16) {
            wmma::fragment<wmma::matrix_a, 16, 16, 16, bft, wmma::row_major> af[2];
            wmma::fragment<wmma::matrix_b, 16, 16, 16, bft, wmma::row_major> bfr[4];
            wmma::load_matrix_sync(af[0], &As[buf][wm][kk], 72);
            wmma::load_matrix_sync(af[1], &As[buf][wm + 16][kk], 72);
#pragma unroll
            for (int j = 0; j < 4; j++)
                wmma::load_matrix_sync(bfr[j], &Bs[buf][kk][wn + j * 16], 136);
#pragma unroll
            for (int i = 0; i < 2; i++)
#pragma unroll
                for (int j = 0; j < 4; j++)
                    wmma::mma_sync(acc[i][j], af[i], bfr[j], acc[i][j]);
        }
        __syncthreads();
    }

    // Epilogue: out = acc + rgb + geo (all fp32)
    float* Cw = reinterpret_cast<float*>(sm) + wid * 1024;
    const size_t bplane = (size_t)bb * Cc * Nn;
#pragma unroll
    for (int i = 0; i < 2; i++) {
#pragma unroll
        for (int j = 0; j < 4; j++)
            wmma::store_matrix_sync(Cw + j * 16, acc[i][j], 64, wmma::mem_row_major);
        __syncwarp();
        const int r = lane >> 1, c0 = (lane & 1) * 32;
        const float* src = Cw + r * 64 + c0;
        const size_t off = bplane + (size_t)(m0 + wm + i * 16 + r) * 4096 + n0 + wn + c0;
#pragma unroll
        for (int q = 0; q < 8; q++) {
            float4 a = reinterpret_cast<const float4*>(src)[q];
            float4 rr = reinterpret_cast<const float4*>(rgb + off)[q];
            float4 gg = reinterpret_cast<const float4*>(geo + off)[q];
            a.x += rr.x + gg.x;
            a.y += rr.y + gg.y;
            a.z += rr.z + gg.z;
            a.w += rr.w + gg.w;
            reinterpret_cast<float4*>(out + off)[q] = a;
        }
        __syncwarp();
    }
}

// ---------------------------------------------------------------------------
// Launch. Input order: 0 rgb_emb, 1 geo_emb, 2 wq_rgb, 3 wk_rgb, 4 wv_rgb,
// 5 wq_point, 6 wk_point, 7 wv_point, 8 proj_r2p, 9 proj_p2r.
// ---------------------------------------------------------------------------
extern "C" void kernel_launch(void* const* d_in, const int* in_sizes, int n_in,
                              void* d_out, int out_size) {
    const float* rgb = (const float*)d_in[0];
    const float* geo = (const float*)d_in[1];

    cudaFuncSetAttribute(k_gemm_qkv, cudaFuncAttributeMaxDynamicSharedMemorySize, 71680);
    cudaFuncSetAttribute(k_gemm_final, cudaFuncAttributeMaxDynamicSharedMemorySize, 71680);
    cudaFuncSetAttribute(k_attn, cudaFuncAttributeMaxDynamicSharedMemorySize, 111616);

    k_convert<<<32768, 256>>>(rgb, geo);
    // weight slot order: 0 wq_rgb, 1 wk_point, 2 wv_point, 3 wq_point, 4 wk_rgb,
    //                    5 wv_rgb, 6 proj_p2r, 7 proj_r2p
    k_convw<<<dim3(256, 8), 256>>>((const float*)d_in[2], (const float*)d_in[6],
                                   (const float*)d_in[7], (const float*)d_in[5],
                                   (const float*)d_in[3], (const float*)d_in[4],
                                   (const float*)d_in[9], (const float*)d_in[8]);

    // QKV projections: 6 combos x 16 batches
    k_gemm_qkv<<<dim3(32, 4, 96), 256, 71680>>>();

    // attention per (branch, batch, head)
    k_attn<<<dim3(8, 16, 2), 256, 111616>>>();

    // fused output projections + residual -> d_out
    k_gemm_final<<<dim3(32, 4, 16), 256, 71680>>>(rgb, geo, (float*)d_out);
}

// round 6
// speedup vs baseline: 1.2000x; 1.0603x over previous
#include <cuda_runtime.h>
#include <cuda_bf16.h>
#include <mma.h>
#include <cstdint>

using namespace nvcuda;
typedef __nv_bfloat16 bft;

constexpr int Bq = 16, Cc = 512, Nn = 4096;

// Scratch (device globals — no allocation allowed)
__device__ __align__(16) bft g_embh[2][Bq][Cc][Nn];   // bf16 rgb/geo
__device__ __align__(16) bft g_qkv[6][Bq][Cc][Nn];    // 0:Qp2r 1:Kp2r 2:Vp2r 3:Qr2p 4:Kr2p 5:Vr2p
__device__ __align__(16) bft g_wbf[8][Cc][Cc];        // 0..5 qkv weights, 6:proj_p2r 7:proj_r2p
__device__ __align__(16) bft g_outb[2][Bq][Cc][Nn];   // attention outputs per branch

// ---------------------------------------------------------------------------
// cp.async helpers
// ---------------------------------------------------------------------------
__device__ __forceinline__ void cp16(void* s, const void* g) {
    unsigned ss = (unsigned)__cvta_generic_to_shared(s);
    asm volatile("cp.async.cg.shared.global [%0], [%1], 16;\n" ::"r"(ss), "l"(g));
}
__device__ __forceinline__ void cpcommit() { asm volatile("cp.async.commit_group;\n"); }
template <int W>
__device__ __forceinline__ void cpwait() { asm volatile("cp.async.wait_group %0;\n" ::"n"(W)); }

// ---------------------------------------------------------------------------
// K1a: convert embeddings fp32 -> bf16
// ---------------------------------------------------------------------------
__global__ void k_convert(const float* __restrict__ rgb, const float* __restrict__ geo) {
    size_t i = (size_t)(blockIdx.x * blockDim.x + threadIdx.x) * 4;
    float4 a = *reinterpret_cast<const float4*>(rgb + i);
    float4 b = *reinterpret_cast<const float4*>(geo + i);
    __nv_bfloat162* pr = reinterpret_cast<__nv_bfloat162*>(&g_embh[0][0][0][0] + i);
    __nv_bfloat162* pg = reinterpret_cast<__nv_bfloat162*>(&g_embh[1][0][0][0] + i);
    pr[0] = __floats2bfloat162_rn(a.x, a.y);
    pr[1] = __floats2bfloat162_rn(a.z, a.w);
    pg[0] = __floats2bfloat162_rn(b.x, b.y);
    pg[1] = __floats2bfloat162_rn(b.z, b.w);
}

// K1b: convert 8 weight matrices fp32 -> bf16
__global__ void k_convw(const float* w0, const float* w1, const float* w2, const float* w3,
                        const float* w4, const float* w5, const float* w6, const float* w7) {
    const float* ws[8] = {w0, w1, w2, w3, w4, w5, w6, w7};
    const int s = blockIdx.y;
    size_t i = (size_t)(blockIdx.x * blockDim.x + threadIdx.x) * 4;
    float4 a = *reinterpret_cast<const float4*>(ws[s] + i);
    __nv_bfloat162* p = reinterpret_cast<__nv_bfloat162*>(&g_wbf[s][0][0] + i);
    p[0] = __floats2bfloat162_rn(a.x, a.y);
    p[1] = __floats2bfloat162_rn(a.z, a.w);
}

// ---------------------------------------------------------------------------
// K2: QKV projections. C[512,4096] = W[512,512] @ X[512,4096].
// Tile 128(M) x 256(N), BK=64, 3-stage cp.async ring, single barrier per chunk.
// 8 warps as 2(M) x 4(N): warp tile 64x64 (acc 4x4).
// smem: As[3][128][72] @0 (55296) | Bs[3][64][264] @55296 (101376) = 156672
// grid=(16 n-tiles, 4 m-tiles, 96 = bb*6+combo), 256 thr
// ---------------------------------------------------------------------------
__global__ __launch_bounds__(256) void k_gemm_qkv() {
    extern __shared__ char sm[];
    bft (*As)[128][72] = reinterpret_cast<bft (*)[128][72]>(sm);
    bft (*Bs)[64][264] = reinterpret_cast<bft (*)[64][264]>(sm + 55296);

    const int z = blockIdx.z;
    const int bb = z / 6, combo = z % 6;
    const int geo_src = (combo >= 1 && combo <= 3) ? 1 : 0;
    const bft* __restrict__ Ag = &g_wbf[combo][0][0];
    const bft* __restrict__ Bg = &g_embh[geo_src][bb][0][0];
    bft* __restrict__ Cg = &g_qkv[combo][bb][0][0];
    const int m0 = blockIdx.y * 128, n0 = blockIdx.x * 256;
    const int tid = threadIdx.x, wid = tid >> 5, lane = tid & 31;
    const int wm = (wid & 1) * 64, wn = (wid >> 1) * 64;

    wmma::fragment<wmma::accumulator, 16, 16, 16, float> acc[4][4];
#pragma unroll
    for (int i = 0; i < 4; i++)
#pragma unroll
        for (int j = 0; j < 4; j++) wmma::fill_fragment(acc[i][j], 0.0f);

    auto pre = [&](int it, int buf) {
        const int k0 = it * 64;
#pragma unroll
        for (int p = 0; p < 4; p++) {
            int idx = tid + p * 256;
            int r = idx >> 3, c = (idx & 7) * 8;
            cp16(&As[buf][r][c], Ag + (m0 + r) * 512 + k0 + c);
        }
#pragma unroll
        for (int p = 0; p < 8; p++) {
            int idx = tid + p * 256;
            int r = idx >> 5, c = (idx & 31) * 8;
            cp16(&Bs[buf][r][c], Bg + (size_t)(k0 + r) * 4096 + n0 + c);
        }
        cpcommit();
    };

    pre(0, 0);
    pre(1, 1);
    for (int it = 0; it < 8; ++it) {
        const int buf = it % 3;
        if (it < 7) cpwait<1>();
        else        cpwait<0>();
        __syncthreads();
        if (it + 2 < 8) pre(it + 2, (it + 2) % 3);
#pragma unroll
        for (int kk = 0; kk < 64; kk += 16) {
            wmma::fragment<wmma::matrix_a, 16, 16, 16, bft, wmma::row_major> af[4];
            wmma::fragment<wmma::matrix_b, 16, 16, 16, bft, wmma::row_major> bfr[4];
#pragma unroll
            for (int i = 0; i < 4; i++)
                wmma::load_matrix_sync(af[i], &As[buf][wm + i * 16][kk], 72);
#pragma unroll
            for (int j = 0; j < 4; j++)
                wmma::load_matrix_sync(bfr[j], &Bs[buf][kk][wn + j * 16], 264);
#pragma unroll
            for (int i = 0; i < 4; i++)
#pragma unroll
                for (int j = 0; j < 4; j++)
                    wmma::mma_sync(acc[i][j], af[i], bfr[j], acc[i][j]);
        }
    }
    __syncthreads();

    // Epilogue: per-warp smem staging (aliases tile smem), fp32 -> bf16.
    float* Cw = reinterpret_cast<float*>(sm) + wid * 1024;
#pragma unroll
    for (int i = 0; i < 4; i++) {
#pragma unroll
        for (int j = 0; j < 4; j++)
            wmma::store_matrix_sync(Cw + j * 16, acc[i][j], 64, wmma::mem_row_major);
        __syncwarp();
        const int r = lane >> 1, c0 = (lane & 1) * 32;
        const float* src = Cw + r * 64 + c0;
        bft* dst = Cg + (size_t)(m0 + wm + i * 16 + r) * 4096 + n0 + wn + c0;
        uint4 o[4];
        __nv_bfloat162* ph = reinterpret_cast<__nv_bfloat162*>(o);
#pragma unroll
        for (int q = 0; q < 16; q++) ph[q] = __floats2bfloat162_rn(src[2 * q], src[2 * q + 1]);
#pragma unroll
        for (int q = 0; q < 4; q++) reinterpret_cast<uint4*>(dst)[q] = o[q];
        __syncwarp();
    }
}

// ---------------------------------------------------------------------------
// K4: fused output projections + residual:
//   out[b] = proj_p2r @ Out0 + proj_r2p @ Out1 + rgb + geo
// Same tiling as K2; 16 chunks (2 branches x 8 k-steps of 64).
// grid=(16,4,16), 256 thr, dyn smem 156672
// ---------------------------------------------------------------------------
__global__ __launch_bounds__(256) void k_gemm_final(const float* __restrict__ rgb,
                                                    const float* __restrict__ geo,
                                                    float* __restrict__ out) {
    extern __shared__ char sm[];
    bft (*As)[128][72] = reinterpret_cast<bft (*)[128][72]>(sm);
    bft (*Bs)[64][264] = reinterpret_cast<bft (*)[64][264]>(sm + 55296);

    const int bb = blockIdx.z;
    const int m0 = blockIdx.y * 128, n0 = blockIdx.x * 256;
    const int tid = threadIdx.x, wid = tid >> 5, lane = tid & 31;
    const int wm = (wid & 1) * 64, wn = (wid >> 1) * 64;

    wmma::fragment<wmma::accumulator, 16, 16, 16, float> acc[4][4];
#pragma unroll
    for (int i = 0; i < 4; i++)
#pragma unroll
        for (int j = 0; j < 4; j++) wmma::fill_fragment(acc[i][j], 0.0f);

    auto pre = [&](int ck, int buf) {
        const int brn = ck >> 3, k0 = (ck & 7) * 64;
        const bft* Ag = &g_wbf[6 + brn][0][0];
        const bft* Bg = &g_outb[brn][bb][0][0];
#pragma unroll
        for (int p = 0; p < 4; p++) {
            int idx = tid + p * 256;
            int r = idx >> 3, c = (idx & 7) * 8;
            cp16(&As[buf][r][c], Ag + (m0 + r) * 512 + k0 + c);
        }
#pragma unroll
        for (int p = 0; p < 8; p++) {
            int idx = tid + p * 256;
            int r = idx >> 5, c = (idx & 31) * 8;
            cp16(&Bs[buf][r][c], Bg + (size_t)(k0 + r) * 4096 + n0 + c);
        }
        cpcommit();
    };

    pre(0, 0);
    pre(1, 1);
    for (int it = 0; it < 16; ++it) {
        const int buf = it % 3;
        if (it < 15) cpwait<1>();
        else         cpwait<0>();
        __syncthreads();
        if (it + 2 < 16) pre(it + 2, (it + 2) % 3);
#pragma unroll
        for (int kk = 0; kk < 64; kk += 16) {
            wmma::fragment<wmma::matrix_a, 16, 16, 16, bft, wmma::row_major> af[4];
            wmma::fragment<wmma::matrix_b, 16, 16, 16, bft, wmma::row_major> bfr[4];
#pragma unroll
            for (int i = 0; i < 4; i++)
                wmma::load_matrix_sync(af[i], &As[buf][wm + i * 16][kk], 72);
#pragma unroll
            for (int j = 0; j < 4; j++)
                wmma::load_matrix_sync(bfr[j], &Bs[buf][kk][wn + j * 16], 264);
#pragma unroll
            for (int i = 0; i < 4; i++)
#pragma unroll
                for (int j = 0; j < 4; j++)
                    wmma::mma_sync(acc[i][j], af[i], bfr[j], acc[i][j]);
        }
    }
    __syncthreads();

    // Epilogue: out = acc + rgb + geo (fp32)
    float* Cw = reinterpret_cast<float*>(sm) + wid * 1024;
    const size_t bplane = (size_t)bb * Cc * Nn;
#pragma unroll
    for (int i = 0; i < 4; i++) {
#pragma unroll
        for (int j = 0; j < 4; j++)
            wmma::store_matrix_sync(Cw + j * 16, acc[i][j], 64, wmma::mem_row_major);
        __syncwarp();
        const int r = lane >> 1, c0 = (lane & 1) * 32;
        const float* src = Cw + r * 64 + c0;
        const size_t off = bplane + (size_t)(m0 + wm + i * 16 + r) * 4096 + n0 + wn + c0;
#pragma unroll
        for (int q = 0; q < 8; q++) {
            float4 a = reinterpret_cast<const float4*>(src)[q];
            float4 rr = reinterpret_cast<const float4*>(rgb + off)[q];
            float4 gg = reinterpret_cast<const float4*>(geo + off)[q];
            a.x += rr.x + gg.x;
            a.y += rr.y + gg.y;
            a.z += rr.z + gg.z;
            a.w += rr.w + gg.w;
            reinterpret_cast<float4*>(out + off)[q] = a;
        }
        __syncwarp();
    }
}

// ---------------------------------------------------------------------------
// K3: XCA attention per (branch, batch, head); 4-stage cp.async, 1 barrier/chunk.
// Phase 1: S[64,64] = Q[64,N].K[64,N]^T; Phase 2: softmax; Phase 3: attn^T @ V.
// grid=(8,16,2), 256 thr. dyn smem 181248:
//   QS[4][64][136] @0 (69632, aliased by VS in p3)
//   KS[4][64][136] @69632 (69632, aliased by output staging in p3)
//   Ls[2][64][64] fp32 @139264 (32768)
//   Ps[64][72] bf16 @172032 (9216)
// ---------------------------------------------------------------------------
__global__ __launch_bounds__(256) void k_attn() {
    extern __shared__ char sm[];
    bft (*QS)[64][136] = reinterpret_cast<bft (*)[64][136]>(sm);
    bft (*KS)[64][136] = reinterpret_cast<bft (*)[64][136]>(sm + 69632);
    float (*Ls)[64][64] = reinterpret_cast<float (*)[64][64]>(sm + 139264);
    bft (*Ps)[72] = reinterpret_cast<bft (*)[72]>(sm + 172032);

    const int h = blockIdx.x, bb = blockIdx.y, br = blockIdx.z;
    const bft* __restrict__ Q  = &g_qkv[br * 3 + 0][bb][h * 64][0];
    const bft* __restrict__ Kk = &g_qkv[br * 3 + 1][bb][h * 64][0];
    const bft* __restrict__ V  = &g_qkv[br * 3 + 2][bb][h * 64][0];
    bft* __restrict__ O = &g_outb[br][bb][h * 64][0];
    const int tid = threadIdx.x, wid = tid >> 5, lane = tid & 31;

    // ---- Phase 1: logits ----
    {
        const int wm = (wid & 3) * 16, kh = wid >> 2;
        wmma::fragment<wmma::accumulator, 16, 16, 16, float> acc[4];
#pragma unroll
        for (int j = 0; j < 4; j++) wmma::fill_fragment(acc[j], 0.0f);

        auto pre = [&](int c, int buf) {
#pragma unroll
            for (int p = 0; p < 4; p++) {
                int idx = tid + p * 256;
                int r = idx >> 4, cl = (idx & 15) * 8;
                cp16(&QS[buf][r][cl], Q + (size_t)r * 4096 + c * 128 + cl);
                cp16(&KS[buf][r][cl], Kk + (size_t)r * 4096 + c * 128 + cl);
            }
            cpcommit();
        };
        pre(0, 0);
        pre(1, 1);
        pre(2, 2);
        for (int c = 0; c < 32; ++c) {
            const int buf = c & 3;
            if (c <= 29)      cpwait<2>();
            else if (c == 30) cpwait<1>();
            else              cpwait<0>();
            __syncthreads();
            if (c + 3 < 32) pre(c + 3, (c + 3) & 3);
#pragma unroll
            for (int ks = 0; ks < 4; ks++) {
                wmma::fragment<wmma::matrix_a, 16, 16, 16, bft, wmma::row_major> af;
                wmma::load_matrix_sync(af, &QS[buf][wm][kh * 64 + ks * 16], 136);
#pragma unroll
                for (int j = 0; j < 4; j++) {
                    wmma::fragment<wmma::matrix_b, 16, 16, 16, bft, wmma::col_major> bfr;
                    wmma::load_matrix_sync(bfr, &KS[buf][j * 16][kh * 64 + ks * 16], 136);
                    wmma::mma_sync(acc[j], af, bfr, acc[j]);
                }
            }
        }
#pragma unroll
        for (int j = 0; j < 4; j++)
            wmma::store_matrix_sync(&Ls[kh][wm][j * 16], acc[j], 64, wmma::mem_row_major);
    }
    __syncthreads();

    // ---- Phase 2: softmax ----
    if (tid < 64) {
        const float scale = 0.125f;
        float mx = -1e30f;
        for (int j = 0; j < 64; j++) {
            float v = (Ls[0][tid][j] + Ls[1][tid][j]) * scale;
            mx = fmaxf(mx, v);
        }
        float s = 0.f;
        for (int j = 0; j < 64; j++) {
            float v = (Ls[0][tid][j] + Ls[1][tid][j]) * scale;
            float e = __expf(v - mx);
            Ls[0][tid][j] = e;
            s += e;
        }
        float inv = 1.0f / s;
        for (int j = 0; j < 64; j++) Ps[tid][j] = __float2bfloat16(Ls[0][tid][j] * inv);
    }
    __syncthreads();

    // ---- Phase 3: OutT = attn^T @ V ----
    {
        bft (*VS)[64][136] = QS;  // alias
        float* OSw = reinterpret_cast<float*>(sm + 69632) + wid * 1024;  // 16x64 per warp
        const int we = (wid & 3), wn = (wid >> 2) * 64;

        wmma::fragment<wmma::matrix_a, 16, 16, 16, bft, wmma::col_major> af[4];
#pragma unroll
        for (int d = 0; d < 4; d++)
            wmma::load_matrix_sync(af[d], &Ps[d * 16][we * 16], 72);

        auto prev = [&](int c, int buf) {
#pragma unroll
            for (int p = 0; p < 4; p++) {
                int idx = tid + p * 256;
                int r = idx >> 4, cl = (idx & 15) * 8;
                cp16(&VS[buf][r][cl], V + (size_t)r * 4096 + c * 128 + cl);
            }
            cpcommit();
        };
        prev(0, 0);
        prev(1, 1);
        prev(2, 2);
        for (int c = 0; c < 32; ++c) {
            const int buf = c & 3;
            if (c <= 29)      cpwait<2>();
            else if (c == 30) cpwait<1>();
            else              cpwait<0>();
            __syncthreads();
            if (c + 3 < 32) prev(c + 3, (c + 3) & 3);
#pragma unroll
            for (int nc = 0; nc < 4; nc++) {
                wmma::fragment<wmma::accumulator, 16, 16, 16, float> oa;
                wmma::fill_fragment(oa, 0.0f);
#pragma unroll
                for (int d = 0; d < 4; d++) {
                    wmma::fragment<wmma::matrix_b, 16, 16, 16, bft, wmma::row_major> bfr;
                    wmma::load_matrix_sync(bfr, &VS[buf][d * 16][wn + nc * 16], 136);
                    wmma::mma_sync(oa, af[d], bfr, oa);
                }
                wmma::store_matrix_sync(OSw + nc * 16, oa, 64, wmma::mem_row_major);
            }
            __syncwarp();
            {
                const int r = lane >> 1, c0 = (lane & 1) * 32;
                const float* src = OSw + r * 64 + c0;
                bft* dst = O + (size_t)(we * 16 + r) * 4096 + c * 128 + wn + c0;
                uint4 o[4];
                __nv_bfloat162* ph = reinterpret_cast<__nv_bfloat162*>(o);
#pragma unroll
                for (int q = 0; q < 16; q++)
                    ph[q] = __floats2bfloat162_rn(src[2 * q], src[2 * q + 1]);
#pragma unroll
                for (int q = 0; q < 4; q++) reinterpret_cast<uint4*>(dst)[q] = o[q];
            }
            __syncwarp();
        }
    }
}

// ---------------------------------------------------------------------------
// Launch. Input order: 0 rgb_emb, 1 geo_emb, 2 wq_rgb, 3 wk_rgb, 4 wv_rgb,
// 5 wq_point, 6 wk_point, 7 wv_point, 8 proj_r2p, 9 proj_p2r.
// ---------------------------------------------------------------------------
extern "C" void kernel_launch(void* const* d_in, const int* in_sizes, int n_in,
                              void* d_out, int out_size) {
    const float* rgb = (const float*)d_in[0];
    const float* geo = (const float*)d_in[1];

    cudaFuncSetAttribute(k_gemm_qkv, cudaFuncAttributeMaxDynamicSharedMemorySize, 156672);
    cudaFuncSetAttribute(k_gemm_final, cudaFuncAttributeMaxDynamicSharedMemorySize, 156672);
    cudaFuncSetAttribute(k_attn, cudaFuncAttributeMaxDynamicSharedMemorySize, 181248);

    k_convert<<<32768, 256>>>(rgb, geo);
    // weight slot order: 0 wq_rgb, 1 wk_point, 2 wv_point, 3 wq_point, 4 wk_rgb,
    //                    5 wv_rgb, 6 proj_p2r, 7 proj_r2p
    k_convw<<<dim3(256, 8), 256>>>((const float*)d_in[2], (const float*)d_in[6],
                                   (const float*)d_in[7], (const float*)d_in[5],
                                   (const float*)d_in[3], (const float*)d_in[4],
                                   (const float*)d_in[9], (const float*)d_in[8]);

    // QKV projections: z = bb*6 + combo (batch-major for L2 reuse of embeddings)
    k_gemm_qkv<<<dim3(16, 4, 96), 256, 156672>>>();

    // attention per (branch, batch, head)
    k_attn<<<dim3(8, 16, 2), 256, 181248>>>();

    // fused output projections + residual -> d_out
    k_gemm_final<<<dim3(16, 4, 16), 256, 156672>>>(rgb, geo, (float*)d_out);
}